// round 9
// baseline (speedup 1.0000x reference)
#include <cuda_runtime.h>
#include <cuda_fp16.h>
#include <cstdint>

#define D       128
#define MAXN    100000
#define MAXE    1700000
#define TILE    1024
#define MAXB    ((MAXN + TILE - 1) / TILE)   // 98

// Scratch (allocation-free contract: __device__ globals)
__device__ float g_deg [MAXN];
__device__ float g_dinv[MAXN];
__device__ int   g_cnt [MAXN];
__device__ int   g_off [MAXN + 1];
__device__ int   g_cur [MAXN];
__device__ volatile unsigned long long g_state[MAXB];  // lookback: flag<<32|value
__device__ __half g_h16[(size_t)MAXN * D];
__device__ __half g_w16[D * D];              // W^T fp16, [n][k] plain
__device__ int2  g_edge[MAXE];               // packed {col, w_bits}
__device__ int   g_is64;

__device__ __forceinline__ uint32_t smem_u32(const void* p) {
    uint32_t a;
    asm("{ .reg .u64 t; cvta.to.shared.u64 t, %1; cvt.u32.u64 %0, t; }"
        : "=r"(a) : "l"(p));
    return a;
}
__device__ __forceinline__ int load_idx(const void* ei, int is64, size_t pos) {
    if (is64) return (int)((const long long*)ei)[pos];
    return ((const int*)ei)[pos];
}
// XOR-swizzled byte address of 16B chunk c8 in row r (row = 128 halves = 256B)
__device__ __forceinline__ uint32_t sw_addr(uint32_t base, int r, int c8) {
    return base + r * 256 + ((c8 ^ (r & 7)) << 4);
}

// ---------------------------------------------------------------------------
// Kernel 1: setup = detect dtype + zero lookback state (block 0),
//           init deg/cnt, convert W.
// ---------------------------------------------------------------------------
__global__ void __launch_bounds__(256)
setup_kernel(const int* __restrict__ ei32, int n_i32,
             const float* __restrict__ W, int N, int nbInit) {
    int b = blockIdx.x;
    if (b == 0) {
        __shared__ int any_nonzero;
        if (threadIdx.x == 0) any_nonzero = 0;
        __syncthreads();
        int n = min(1024, n_i32 / 2);
        for (int i = threadIdx.x; i < n; i += blockDim.x)
            if (ei32[2 * i + 1] != 0) any_nonzero = 1;
        __syncthreads();
        if (threadIdx.x == 0) g_is64 = (any_nonzero == 0) ? 1 : 0;
        if (threadIdx.x < MAXB) g_state[threadIdx.x] = 0ull;
    } else if (b <= nbInit) {
        int i = (b - 1) * 256 + threadIdx.x;
        if (i < N) { g_deg[i] = 1.0f; g_cnt[i] = 0; }
    } else {
        int i = (b - nbInit - 1) * 256 + threadIdx.x;   // 0..16383
        if (i < D * D) {
            int n = i >> 7, k = i & 127;
            g_w16[n * D + k] = __float2half_rn(W[k * D + n]);
        }
    }
}

// ---------------------------------------------------------------------------
// Kernel 2: deg[row] += w ; cnt[row]++
// ---------------------------------------------------------------------------
__global__ void accum_deg_kernel(const void* __restrict__ ei,
                                 const float* __restrict__ ew, int E) {
    int i = blockIdx.x * blockDim.x + threadIdx.x;
    if (i < E) {
        int r = load_idx(ei, g_is64, i);
        atomicAdd(&g_deg[r], ew[i]);
        atomicAdd(&g_cnt[r], 1);
    }
}

// ---------------------------------------------------------------------------
// Kernel 3: single-pass exclusive scan of g_cnt (decoupled lookback),
//           also g_cur init and dinv = rsqrt(deg).
// ---------------------------------------------------------------------------
__device__ __forceinline__ int warp_incl_scan(int v) {
    #pragma unroll
    for (int d = 1; d < 32; d <<= 1) {
        int u = __shfl_up_sync(0xffffffff, v, d);
        if ((threadIdx.x & 31) >= d) v += u;
    }
    return v;
}

__global__ void __launch_bounds__(TILE)
scan_lookback(int N, int nb) {
    __shared__ int ws[32];
    __shared__ int s_base;
    const int b = blockIdx.x;
    const int t = threadIdx.x;
    const int i = b * TILE + t;
    int v = (i < N) ? g_cnt[i] : 0;
    int lane = t & 31, wid = t >> 5;
    int s = warp_incl_scan(v);
    if (lane == 31) ws[wid] = s;
    __syncthreads();
    if (wid == 0) ws[lane] = warp_incl_scan(ws[lane]);
    __syncthreads();
    int incl  = s + (wid > 0 ? ws[wid - 1] : 0);   // inclusive within block
    int total = ws[31];                            // block aggregate

    if (t == 0) {
        int run = 0;
        if (b == 0) {
            g_state[0] = (2ull << 32) | (unsigned)total;   // prefix ready
        } else {
            g_state[b] = (1ull << 32) | (unsigned)total;   // aggregate ready
            int j = b - 1;
            while (true) {
                unsigned long long st;
                do { st = g_state[j]; } while ((st >> 32) == 0ull);
                run += (int)(unsigned)st;
                if ((st >> 32) == 2ull) break;
                j--;
            }
            g_state[b] = (2ull << 32) | (unsigned)(run + total);
        }
        s_base = run;
    }
    __syncthreads();
    const int base = s_base;
    if (i < N) {
        int off = base + incl - v;                 // exclusive prefix
        g_off[i] = off;
        g_cur[i] = off;
        float dg = g_deg[i];
        g_dinv[i] = (dg > 0.0f) ? rsqrtf(dg) : 0.0f;
    }
    if (b == nb - 1 && t == TILE - 1) g_off[N] = base + incl;
}

// ---------------------------------------------------------------------------
// Kernel 4 (fused): blocks [0, nbG) = HMMA GEMM tile; [nbG, ...) = bucket.
// GEMM: 64 rows/CTA, h = x @ W, fp16 in / fp32 acc / fp16 out.
// ---------------------------------------------------------------------------
__global__ void __launch_bounds__(256)
fused_gemm_bucket(const float* __restrict__ x,
                  const void* __restrict__ ei,
                  const float* __restrict__ ew,
                  int N, int E, int nbG) {
    extern __shared__ __align__(16) char smem[];

    if (blockIdx.x >= nbG) {
        // ----- bucket path -----
        int i = (blockIdx.x - nbG) * 256 + threadIdx.x;
        if (i < E) {
            const int is64 = g_is64;
            int r = load_idx(ei, is64, i);
            int c = load_idx(ei, is64, (size_t)E + i);
            int pos = atomicAdd(&g_cur[r], 1);
            float wn = ew[i] * g_dinv[r] * g_dinv[c];
            g_edge[pos] = make_int2(c, __float_as_int(wn));
        }
        return;
    }

    // ----- GEMM path -----
    const uint32_t xs = smem_u32(smem);          // A tile: 64 x 128 f16 (16KB)
    const uint32_t ws = xs + 16384;              // B tile: 128 x 128 f16 (32KB)
    const int tid  = threadIdx.x;
    const int lane = tid & 31;
    const int wid  = tid >> 5;
    const int r0   = blockIdx.x * 64;

    // Load x tile -> fp16 swizzled. 1024 chunks of 16B; 4 per thread.
    #pragma unroll
    for (int it = 0; it < 4; it++) {
        int id = tid + it * 256;                 // 0..1023
        int rl = id >> 4, c8 = id & 15;
        int r  = r0 + rl;
        __half hv[8];
        if (r < N) {
            const float4* src = (const float4*)(x + (size_t)r * D + c8 * 8);
            float4 f0 = src[0], f1 = src[1];
            hv[0]=__float2half_rn(f0.x); hv[1]=__float2half_rn(f0.y);
            hv[2]=__float2half_rn(f0.z); hv[3]=__float2half_rn(f0.w);
            hv[4]=__float2half_rn(f1.x); hv[5]=__float2half_rn(f1.y);
            hv[6]=__float2half_rn(f1.z); hv[7]=__float2half_rn(f1.w);
        } else {
            #pragma unroll
            for (int k = 0; k < 8; k++) hv[k] = __ushort_as_half((unsigned short)0);
        }
        asm volatile("st.shared.v4.b32 [%0], {%1,%2,%3,%4};"
                     :: "r"(sw_addr(xs, rl, c8)),
                        "r"(((uint32_t*)hv)[0]), "r"(((uint32_t*)hv)[1]),
                        "r"(((uint32_t*)hv)[2]), "r"(((uint32_t*)hv)[3]) : "memory");
    }

    // Load W^T tile (g_w16 [n][k]) -> swizzled. 2048 chunks; 8 per thread.
    #pragma unroll
    for (int it = 0; it < 8; it++) {
        int id = tid + it * 256;                 // 0..2047
        int n = id >> 4, c8 = id & 15;
        uint4 q = *(const uint4*)(g_w16 + n * D + c8 * 8);
        asm volatile("st.shared.v4.b32 [%0], {%1,%2,%3,%4};"
                     :: "r"(sw_addr(ws, n, c8)),
                        "r"(q.x), "r"(q.y), "r"(q.z), "r"(q.w) : "memory");
    }
    __syncthreads();

    // Warp layout: 4 M-warps x 2 N-halves
    const int wm = wid & 3;                      // rows wm*16 .. +16
    const int wn = wid >> 2;                     // cols wn*64 .. +64

    float d[8][4];
    #pragma unroll
    for (int t = 0; t < 8; t++)
        #pragma unroll
        for (int k = 0; k < 4; k++) d[t][k] = 0.0f;

    const int lr  = lane & 7;
    const int sel = lane >> 3;                   // 0..3

    #pragma unroll
    for (int ks = 0; ks < 8; ks++) {
        // A frag: m16k16, ldmatrix x4
        int arow = wm * 16 + lr + ((sel & 1) << 3);
        int ac8  = ks * 2 + ((sel >> 1) & 1);
        uint32_t a0, a1, a2, a3;
        asm volatile("ldmatrix.sync.aligned.m8n8.x4.shared.b16 {%0,%1,%2,%3}, [%4];"
                     : "=r"(a0), "=r"(a1), "=r"(a2), "=r"(a3)
                     : "r"(sw_addr(xs, arow, ac8)));

        #pragma unroll
        for (int nt = 0; nt < 8; nt++) {
            int n0 = wn * 64 + nt * 8;
            int brow = n0 + lr;
            int bc8  = ks * 2 + ((lane >> 3) & 1);
            uint32_t b0, b1;
            asm volatile("ldmatrix.sync.aligned.m8n8.x2.shared.b16 {%0,%1}, [%2];"
                         : "=r"(b0), "=r"(b1)
                         : "r"(sw_addr(ws, brow, bc8)));
            asm volatile(
                "mma.sync.aligned.m16n8k16.row.col.f32.f16.f16.f32 "
                "{%0,%1,%2,%3}, {%4,%5,%6,%7}, {%8,%9}, {%0,%1,%2,%3};"
                : "+f"(d[nt][0]), "+f"(d[nt][1]), "+f"(d[nt][2]), "+f"(d[nt][3])
                : "r"(a0), "r"(a1), "r"(a2), "r"(a3), "r"(b0), "r"(b1));
        }
    }

    // Epilogue: write fp16 h. Lane l owns rows (l/4, l/4+8), cols 2*(l%4)+{0,1}.
    const int er = r0 + wm * 16 + (lane >> 2);
    const int ec = wn * 64 + ((lane & 3) << 1);
    #pragma unroll
    for (int nt = 0; nt < 8; nt++) {
        int col = ec + nt * 8;
        if (er < N) {
            __half2 v = __floats2half2_rn(d[nt][0], d[nt][1]);
            *(__half2*)(g_h16 + (size_t)er * D + col) = v;
        }
        if (er + 8 < N) {
            __half2 v = __floats2half2_rn(d[nt][2], d[nt][3]);
            *(__half2*)(g_h16 + (size_t)(er + 8) * D + col) = v;
        }
    }
}

// ---------------------------------------------------------------------------
// Kernel 5: per-row gather (fp16 h). One warp per row (R5 version, fastest).
// ---------------------------------------------------------------------------
__device__ __forceinline__ float4 load_h4(int row, int lane) {
    uint2 raw = ((const uint2*)(g_h16 + (size_t)row * D))[lane];
    __half2 a = *(__half2*)&raw.x;
    __half2 b = *(__half2*)&raw.y;
    float2 fa = __half22float2(a);
    float2 fb = __half22float2(b);
    return make_float4(fa.x, fa.y, fb.x, fb.y);
}

__global__ void __launch_bounds__(128)
gather_kernel(const float* __restrict__ bias,
              float* __restrict__ out, int N) {
    const int warp = (blockIdx.x * blockDim.x + threadIdx.x) >> 5;
    const int lane = threadIdx.x & 31;
    if (warp >= N) return;
    const int row = warp;

    const int s = g_off[row];
    const int e = g_off[row + 1];

    float dv = g_dinv[row];
    float ws = dv * dv;
    float4 hv = load_h4(row, lane);
    float4 acc = make_float4(ws * hv.x, ws * hv.y, ws * hv.z, ws * hv.w);

    int j = s;
    int2 e0 = make_int2(0, 0);
    if (j < e) e0 = g_edge[j];
    while (j < e) {
        int jn = j + 1;
        int2 e1 = make_int2(0, 0);
        if (jn < e) e1 = g_edge[jn];
        float w0 = __int_as_float(e0.y);
        float4 v = load_h4(e0.x, lane);
        acc.x += w0 * v.x; acc.y += w0 * v.y;
        acc.z += w0 * v.z; acc.w += w0 * v.w;
        e0 = e1; j = jn;
    }

    float4 b = ((const float4*)bias)[lane];
    acc.x += b.x; acc.y += b.y; acc.z += b.z; acc.w += b.w;
    ((float4*)(out + (size_t)row * D))[lane] = acc;
}

// ---------------------------------------------------------------------------
extern "C" void kernel_launch(void* const* d_in, const int* in_sizes, int n_in,
                              void* d_out, int out_size) {
    const float* x    = (const float*)d_in[0];    // [N, 128]
    const void*  ei   = d_in[1];                  // [2, E] int64-or-int32
    const float* ew   = (const float*)d_in[2];    // [E]
    const float* W    = (const float*)d_in[3];    // [128, 128]
    const float* bias = (const float*)d_in[4];    // [128]
    float*       out  = (float*)d_out;            // [N, 128]

    const int N = in_sizes[0] / D;
    const int E = in_sizes[2];
    const int nb = (N + TILE - 1) / TILE;
    const int nbInit = (N + 255) / 256;
    const int nbG = (N + 63) / 64;                // gemm blocks
    const int nbE = (E + 255) / 256;              // bucket blocks

    setup_kernel<<<1 + nbInit + 64, 256>>>((const int*)ei, 2 * E, W, N, nbInit);
    accum_deg_kernel<<<(E + 255) / 256, 256>>>(ei, ew, E);
    scan_lookback<<<nb, TILE>>>(N, nb);
    fused_gemm_bucket<<<nbG + nbE, 256, 49152>>>(x, ei, ew, N, E, nbG);

    int blocks = (N * 32 + 127) / 128;            // one warp per row
    gather_kernel<<<blocks, 128>>>(bias, out, N);
}

// round 10
// speedup vs baseline: 1.0426x; 1.0426x over previous
#include <cuda_runtime.h>
#include <cuda_fp16.h>
#include <cstdint>

#define D       128
#define MAXN    100000
#define MAXE    1700000
#define TILE    1024
#define MAXB    ((MAXN + TILE - 1) / TILE)   // 98

// Scratch (allocation-free contract: __device__ globals)
__device__ float g_deg [MAXN];
__device__ float g_dinv[MAXN];
__device__ int   g_cnt [MAXN];
__device__ int   g_off [MAXN + 1];
__device__ int   g_cur [MAXN];
__device__ int   g_bsum[MAXB];
__device__ int   g_bpre[MAXB];
__device__ __half g_h16[(size_t)MAXN * D];
__device__ __half g_w16[D * D];              // W^T fp16, [n][k] plain
__device__ int2  g_edge[MAXE];               // packed {col, w_bits}
__device__ int   g_is64;

__device__ __forceinline__ uint32_t smem_u32(const void* p) {
    uint32_t a;
    asm("{ .reg .u64 t; cvta.to.shared.u64 t, %1; cvt.u32.u64 %0, t; }"
        : "=r"(a) : "l"(p));
    return a;
}
__device__ __forceinline__ int load_idx(const void* ei, int is64, size_t pos) {
    if (is64) return (int)((const long long*)ei)[pos];
    return ((const int*)ei)[pos];
}
// XOR-swizzled byte address of 16B chunk c8 in row r (row = 128 halves = 256B)
__device__ __forceinline__ uint32_t sw_addr(uint32_t base, int r, int c8) {
    return base + r * 256 + ((c8 ^ (r & 7)) << 4);
}

// ---------------------------------------------------------------------------
// Kernel 1: setup = detect dtype (block 0) + init deg/cnt + convert W
// ---------------------------------------------------------------------------
__global__ void __launch_bounds__(256)
setup_kernel(const int* __restrict__ ei32, int n_i32,
             const float* __restrict__ W, int N, int nbInit) {
    int b = blockIdx.x;
    if (b == 0) {
        __shared__ int any_nonzero;
        if (threadIdx.x == 0) any_nonzero = 0;
        __syncthreads();
        int n = min(1024, n_i32 / 2);
        for (int i = threadIdx.x; i < n; i += blockDim.x)
            if (ei32[2 * i + 1] != 0) any_nonzero = 1;
        __syncthreads();
        if (threadIdx.x == 0) g_is64 = (any_nonzero == 0) ? 1 : 0;
    } else if (b <= nbInit) {
        int i = (b - 1) * 256 + threadIdx.x;
        if (i < N) { g_deg[i] = 1.0f; g_cnt[i] = 0; }
    } else {
        int i = (b - nbInit - 1) * 256 + threadIdx.x;   // 0..16383
        if (i < D * D) {
            int n = i >> 7, k = i & 127;
            g_w16[n * D + k] = __float2half_rn(W[k * D + n]);
        }
    }
}

// ---------------------------------------------------------------------------
// Kernel 2: deg[row] += w ; cnt[row]++   (4 edges per thread, batched ILP)
// ---------------------------------------------------------------------------
__global__ void __launch_bounds__(256)
accum_deg_kernel(const void* __restrict__ ei,
                 const float* __restrict__ ew, int E) {
    const int base = blockIdx.x * 1024 + threadIdx.x;
    const int is64 = g_is64;
    int   r[4];
    float w[4];
    #pragma unroll
    for (int u = 0; u < 4; u++) {
        int i = base + u * 256;
        if (i < E) { r[u] = load_idx(ei, is64, i); w[u] = ew[i]; }
        else       { r[u] = -1; w[u] = 0.0f; }
    }
    #pragma unroll
    for (int u = 0; u < 4; u++) {
        if (r[u] >= 0) {
            atomicAdd(&g_deg[r[u]], w[u]);
            atomicAdd(&g_cnt[r[u]], 1);
        }
    }
}

// ---------------------------------------------------------------------------
// 3-phase hierarchical exclusive scan (proven in R8)
// ---------------------------------------------------------------------------
__device__ __forceinline__ int warp_incl_scan(int v) {
    #pragma unroll
    for (int d = 1; d < 32; d <<= 1) {
        int u = __shfl_up_sync(0xffffffff, v, d);
        if ((threadIdx.x & 31) >= d) v += u;
    }
    return v;
}

__global__ void __launch_bounds__(TILE)
scan_pass1(int N) {
    __shared__ int ws[32];
    int i = blockIdx.x * TILE + threadIdx.x;
    int v = (i < N) ? g_cnt[i] : 0;
    int lane = threadIdx.x & 31, wid = threadIdx.x >> 5;
    int s = warp_incl_scan(v);
    if (lane == 31) ws[wid] = s;
    __syncthreads();
    if (wid == 0) {
        int u = ws[lane];
        u = warp_incl_scan(u);
        if (lane == 31) g_bsum[blockIdx.x] = u;
    }
}

__global__ void __launch_bounds__(TILE)
scan_pass2(int nb, int N) {
    __shared__ int ws[32];
    int t = threadIdx.x;
    int v = (t < nb) ? g_bsum[t] : 0;
    int lane = t & 31, wid = t >> 5;
    int s = warp_incl_scan(v);
    if (lane == 31) ws[wid] = s;
    __syncthreads();
    if (wid == 0) ws[lane] = warp_incl_scan(ws[lane]);
    __syncthreads();
    int incl = s + (wid > 0 ? ws[wid - 1] : 0);
    if (t < nb) g_bpre[t] = incl - v;
    if (t == nb - 1) g_off[N] = incl;
}

__global__ void __launch_bounds__(TILE)
scan_pass3(int N) {
    __shared__ int ws[32];
    int i = blockIdx.x * TILE + threadIdx.x;
    int v = (i < N) ? g_cnt[i] : 0;
    int lane = threadIdx.x & 31, wid = threadIdx.x >> 5;
    int s = warp_incl_scan(v);
    if (lane == 31) ws[wid] = s;
    __syncthreads();
    if (wid == 0) ws[lane] = warp_incl_scan(ws[lane]);
    __syncthreads();
    int excl = s - v + (wid > 0 ? ws[wid - 1] : 0) + g_bpre[blockIdx.x];
    if (i < N) {
        g_off[i] = excl;
        g_cur[i] = excl;
        float dg = g_deg[i];
        g_dinv[i] = (dg > 0.0f) ? rsqrtf(dg) : 0.0f;
    }
}

// ---------------------------------------------------------------------------
// Kernel 4 (fused): blocks [0, nbG) = HMMA GEMM tile; [nbG, ...) = bucket
// (4 edges per thread, batched ILP).
// ---------------------------------------------------------------------------
__global__ void __launch_bounds__(256)
fused_gemm_bucket(const float* __restrict__ x,
                  const void* __restrict__ ei,
                  const float* __restrict__ ew,
                  int N, int E, int nbG) {
    extern __shared__ __align__(16) char smem[];

    if (blockIdx.x >= nbG) {
        // ----- bucket path: 1024 edges per block, 4 per thread -----
        const int base = (blockIdx.x - nbG) * 1024 + threadIdx.x;
        const int is64 = g_is64;
        int   r[4], c[4];
        float w[4];
        #pragma unroll
        for (int u = 0; u < 4; u++) {
            int i = base + u * 256;
            if (i < E) {
                r[u] = load_idx(ei, is64, i);
                c[u] = load_idx(ei, is64, (size_t)E + i);
                w[u] = ew[i];
            } else r[u] = -1;
        }
        float dr[4], dc[4];
        #pragma unroll
        for (int u = 0; u < 4; u++)
            if (r[u] >= 0) { dr[u] = g_dinv[r[u]]; dc[u] = g_dinv[c[u]]; }
        int pos[4];
        #pragma unroll
        for (int u = 0; u < 4; u++)
            if (r[u] >= 0) pos[u] = atomicAdd(&g_cur[r[u]], 1);
        #pragma unroll
        for (int u = 0; u < 4; u++)
            if (r[u] >= 0)
                g_edge[pos[u]] = make_int2(c[u],
                                 __float_as_int(w[u] * dr[u] * dc[u]));
        return;
    }

    // ----- GEMM path -----
    const uint32_t xs = smem_u32(smem);          // A tile: 64 x 128 f16 (16KB)
    const uint32_t ws = xs + 16384;              // B tile: 128 x 128 f16 (32KB)
    const int tid  = threadIdx.x;
    const int lane = tid & 31;
    const int wid  = tid >> 5;
    const int r0   = blockIdx.x * 64;

    // Load x tile -> fp16 swizzled. 1024 chunks of 16B; 4 per thread.
    #pragma unroll
    for (int it = 0; it < 4; it++) {
        int id = tid + it * 256;                 // 0..1023
        int rl = id >> 4, c8 = id & 15;
        int r  = r0 + rl;
        __half hv[8];
        if (r < N) {
            const float4* src = (const float4*)(x + (size_t)r * D + c8 * 8);
            float4 f0 = src[0], f1 = src[1];
            hv[0]=__float2half_rn(f0.x); hv[1]=__float2half_rn(f0.y);
            hv[2]=__float2half_rn(f0.z); hv[3]=__float2half_rn(f0.w);
            hv[4]=__float2half_rn(f1.x); hv[5]=__float2half_rn(f1.y);
            hv[6]=__float2half_rn(f1.z); hv[7]=__float2half_rn(f1.w);
        } else {
            #pragma unroll
            for (int k = 0; k < 8; k++) hv[k] = __ushort_as_half((unsigned short)0);
        }
        asm volatile("st.shared.v4.b32 [%0], {%1,%2,%3,%4};"
                     :: "r"(sw_addr(xs, rl, c8)),
                        "r"(((uint32_t*)hv)[0]), "r"(((uint32_t*)hv)[1]),
                        "r"(((uint32_t*)hv)[2]), "r"(((uint32_t*)hv)[3]) : "memory");
    }

    // Load W^T tile (g_w16 [n][k]) -> swizzled. 2048 chunks; 8 per thread.
    #pragma unroll
    for (int it = 0; it < 8; it++) {
        int id = tid + it * 256;                 // 0..2047
        int n = id >> 4, c8 = id & 15;
        uint4 q = *(const uint4*)(g_w16 + n * D + c8 * 8);
        asm volatile("st.shared.v4.b32 [%0], {%1,%2,%3,%4};"
                     :: "r"(sw_addr(ws, n, c8)),
                        "r"(q.x), "r"(q.y), "r"(q.z), "r"(q.w) : "memory");
    }
    __syncthreads();

    // Warp layout: 4 M-warps x 2 N-halves
    const int wm = wid & 3;                      // rows wm*16 .. +16
    const int wn = wid >> 2;                     // cols wn*64 .. +64

    float d[8][4];
    #pragma unroll
    for (int t = 0; t < 8; t++)
        #pragma unroll
        for (int k = 0; k < 4; k++) d[t][k] = 0.0f;

    const int lr  = lane & 7;
    const int sel = lane >> 3;                   // 0..3

    #pragma unroll
    for (int ks = 0; ks < 8; ks++) {
        int arow = wm * 16 + lr + ((sel & 1) << 3);
        int ac8  = ks * 2 + ((sel >> 1) & 1);
        uint32_t a0, a1, a2, a3;
        asm volatile("ldmatrix.sync.aligned.m8n8.x4.shared.b16 {%0,%1,%2,%3}, [%4];"
                     : "=r"(a0), "=r"(a1), "=r"(a2), "=r"(a3)
                     : "r"(sw_addr(xs, arow, ac8)));

        #pragma unroll
        for (int nt = 0; nt < 8; nt++) {
            int n0 = wn * 64 + nt * 8;
            int brow = n0 + lr;
            int bc8  = ks * 2 + ((lane >> 3) & 1);
            uint32_t b0, b1;
            asm volatile("ldmatrix.sync.aligned.m8n8.x2.shared.b16 {%0,%1}, [%2];"
                         : "=r"(b0), "=r"(b1)
                         : "r"(sw_addr(ws, brow, bc8)));
            asm volatile(
                "mma.sync.aligned.m16n8k16.row.col.f32.f16.f16.f32 "
                "{%0,%1,%2,%3}, {%4,%5,%6,%7}, {%8,%9}, {%0,%1,%2,%3};"
                : "+f"(d[nt][0]), "+f"(d[nt][1]), "+f"(d[nt][2]), "+f"(d[nt][3])
                : "r"(a0), "r"(a1), "r"(a2), "r"(a3), "r"(b0), "r"(b1));
        }
    }

    // Epilogue: write fp16 h.
    const int er = r0 + wm * 16 + (lane >> 2);
    const int ec = wn * 64 + ((lane & 3) << 1);
    #pragma unroll
    for (int nt = 0; nt < 8; nt++) {
        int col = ec + nt * 8;
        if (er < N) {
            __half2 v = __floats2half2_rn(d[nt][0], d[nt][1]);
            *(__half2*)(g_h16 + (size_t)er * D + col) = v;
        }
        if (er + 8 < N) {
            __half2 v = __floats2half2_rn(d[nt][2], d[nt][3]);
            *(__half2*)(g_h16 + (size_t)(er + 8) * D + col) = v;
        }
    }
}

// ---------------------------------------------------------------------------
// Kernel 5: per-row gather (fp16 h). One warp per row (R5 version, fastest).
// ---------------------------------------------------------------------------
__device__ __forceinline__ float4 load_h4(int row, int lane) {
    uint2 raw = ((const uint2*)(g_h16 + (size_t)row * D))[lane];
    __half2 a = *(__half2*)&raw.x;
    __half2 b = *(__half2*)&raw.y;
    float2 fa = __half22float2(a);
    float2 fb = __half22float2(b);
    return make_float4(fa.x, fa.y, fb.x, fb.y);
}

__global__ void __launch_bounds__(128)
gather_kernel(const float* __restrict__ bias,
              float* __restrict__ out, int N) {
    const int warp = (blockIdx.x * blockDim.x + threadIdx.x) >> 5;
    const int lane = threadIdx.x & 31;
    if (warp >= N) return;
    const int row = warp;

    const int s = g_off[row];
    const int e = g_off[row + 1];

    float dv = g_dinv[row];
    float ws = dv * dv;
    float4 hv = load_h4(row, lane);
    float4 acc = make_float4(ws * hv.x, ws * hv.y, ws * hv.z, ws * hv.w);

    int j = s;
    int2 e0 = make_int2(0, 0);
    if (j < e) e0 = g_edge[j];
    while (j < e) {
        int jn = j + 1;
        int2 e1 = make_int2(0, 0);
        if (jn < e) e1 = g_edge[jn];
        float w0 = __int_as_float(e0.y);
        float4 v = load_h4(e0.x, lane);
        acc.x += w0 * v.x; acc.y += w0 * v.y;
        acc.z += w0 * v.z; acc.w += w0 * v.w;
        e0 = e1; j = jn;
    }

    float4 b = ((const float4*)bias)[lane];
    acc.x += b.x; acc.y += b.y; acc.z += b.z; acc.w += b.w;
    ((float4*)(out + (size_t)row * D))[lane] = acc;
}

// ---------------------------------------------------------------------------
extern "C" void kernel_launch(void* const* d_in, const int* in_sizes, int n_in,
                              void* d_out, int out_size) {
    const float* x    = (const float*)d_in[0];    // [N, 128]
    const void*  ei   = d_in[1];                  // [2, E] int64-or-int32
    const float* ew   = (const float*)d_in[2];    // [E]
    const float* W    = (const float*)d_in[3];    // [128, 128]
    const float* bias = (const float*)d_in[4];    // [128]
    float*       out  = (float*)d_out;            // [N, 128]

    const int N = in_sizes[0] / D;
    const int E = in_sizes[2];
    const int nb = (N + TILE - 1) / TILE;
    const int nbInit = (N + 255) / 256;
    const int nbG = (N + 63) / 64;                // gemm blocks
    const int nbE = (E + 1023) / 1024;            // bucket blocks (4 edges/thr)

    setup_kernel<<<1 + nbInit + 64, 256>>>((const int*)ei, 2 * E, W, N, nbInit);
    accum_deg_kernel<<<(E + 1023) / 1024, 256>>>(ei, ew, E);
    scan_pass1<<<nb, TILE>>>(N);
    scan_pass2<<<1, TILE>>>(nb, N);
    scan_pass3<<<nb, TILE>>>(N);
    fused_gemm_bucket<<<nbG + nbE, 256, 49152>>>(x, ei, ew, N, E, nbG);

    int blocks = (N * 32 + 127) / 128;            // one warp per row
    gather_kernel<<<blocks, 128>>>(bias, out, N);
}